// round 4
// baseline (speedup 1.0000x reference)
#include <cuda_runtime.h>
#include <cuda_bf16.h>
#include <cstdint>

#define NROWS  100000
#define NFEAT  256
#define NOUT   128
#define NEDGES 3200000

// Device-global scratch (allocation APIs forbidden).
__device__ float g_h[(size_t)NROWS * NOUT];          // 51.2 MB projected features
__device__ uint2 g_edge[NEDGES];                     // 25.6 MB row-sorted (col, val)
__device__ int   g_cnt[NROWS];
__device__ int   g_off[NROWS + 1];
__device__ int   g_cur[NROWS];

// ---------------------------------------------------------------------------
// GEMM: h = x @ W.  128x128 block tile, K-chunks of 16, 8x8 per thread,
// double-buffered SMEM (one __syncthreads per K-chunk).
// ---------------------------------------------------------------------------
__global__ __launch_bounds__(256, 2)
void gcn_gemm_kernel(const float* __restrict__ x, const float* __restrict__ W) {
    __shared__ float As[2][16][128];   // [buf][k][row]
    __shared__ float Bs[2][16][128];   // [buf][k][col]

    const int block_row = blockIdx.x * 128;
    const int t  = threadIdx.x;
    const int tx = t & 15;
    const int ty = t >> 4;

    // Per-thread load slots (2 float4 for A, 2 for B)
    const int a_idx0 = t, a_idx1 = t + 256;
    const int a_r0 = a_idx0 >> 2, a_k0 = (a_idx0 & 3) * 4;
    const int a_r1 = a_idx1 >> 2, a_k1 = (a_idx1 & 3) * 4;
    const int b_idx0 = t, b_idx1 = t + 256;
    const int b_k0 = b_idx0 >> 5, b_c0 = (b_idx0 & 31) * 4;
    const int b_k1 = b_idx1 >> 5, b_c1 = (b_idx1 & 31) * 4;

    float acc[8][8];
    #pragma unroll
    for (int i = 0; i < 8; i++)
        #pragma unroll
        for (int j = 0; j < 8; j++)
            acc[i][j] = 0.0f;

    float4 ra0, ra1, rb0, rb1;

    auto load_chunk = [&](int kc) {
        const int k0 = kc * 16;
        int g0 = block_row + a_r0;
        int g1 = block_row + a_r1;
        ra0 = (g0 < NROWS) ? *(const float4*)(x + (size_t)g0 * NFEAT + k0 + a_k0)
                           : make_float4(0.f, 0.f, 0.f, 0.f);
        ra1 = (g1 < NROWS) ? *(const float4*)(x + (size_t)g1 * NFEAT + k0 + a_k1)
                           : make_float4(0.f, 0.f, 0.f, 0.f);
        rb0 = *(const float4*)(W + (size_t)(k0 + b_k0) * NOUT + b_c0);
        rb1 = *(const float4*)(W + (size_t)(k0 + b_k1) * NOUT + b_c1);
    };
    auto store_chunk = [&](int buf) {
        As[buf][a_k0 + 0][a_r0] = ra0.x;
        As[buf][a_k0 + 1][a_r0] = ra0.y;
        As[buf][a_k0 + 2][a_r0] = ra0.z;
        As[buf][a_k0 + 3][a_r0] = ra0.w;
        As[buf][a_k1 + 0][a_r1] = ra1.x;
        As[buf][a_k1 + 1][a_r1] = ra1.y;
        As[buf][a_k1 + 2][a_r1] = ra1.z;
        As[buf][a_k1 + 3][a_r1] = ra1.w;
        *(float4*)&Bs[buf][b_k0][b_c0] = rb0;
        *(float4*)&Bs[buf][b_k1][b_c1] = rb1;
    };

    load_chunk(0);
    store_chunk(0);
    __syncthreads();

    int buf = 0;
    #pragma unroll 1
    for (int kc = 0; kc < 16; kc++) {
        if (kc + 1 < 16) load_chunk(kc + 1);

        #pragma unroll
        for (int k = 0; k < 16; k++) {
            float a[8], b[8];
            *(float4*)&a[0] = *(const float4*)&As[buf][k][ty * 8];
            *(float4*)&a[4] = *(const float4*)&As[buf][k][ty * 8 + 4];
            *(float4*)&b[0] = *(const float4*)&Bs[buf][k][tx * 8];
            *(float4*)&b[4] = *(const float4*)&Bs[buf][k][tx * 8 + 4];
            #pragma unroll
            for (int i = 0; i < 8; i++)
                #pragma unroll
                for (int j = 0; j < 8; j++)
                    acc[i][j] += a[i] * b[j];
        }

        if (kc + 1 < 16) store_chunk(buf ^ 1);
        __syncthreads();
        buf ^= 1;
    }

    #pragma unroll
    for (int i = 0; i < 8; i++) {
        int grow = block_row + ty * 8 + i;
        if (grow < NROWS) {
            float* hp = g_h + (size_t)grow * NOUT + tx * 8;
            *(float4*)(hp + 0) = make_float4(acc[i][0], acc[i][1], acc[i][2], acc[i][3]);
            *(float4*)(hp + 4) = make_float4(acc[i][4], acc[i][5], acc[i][6], acc[i][7]);
        }
    }
}

// ---------------------------------------------------------------------------
// Binning pipeline: zero counts -> histogram -> scan -> scatter
// (independent of GEMM; overlapped with it via a second capture branch)
// ---------------------------------------------------------------------------
__global__ void gcn_zero_cnt_kernel() {
    int i = blockIdx.x * blockDim.x + threadIdx.x;
    if (i < NROWS) g_cnt[i] = 0;
}

__global__ __launch_bounds__(256)
void gcn_hist_kernel(const int* __restrict__ er) {
    int stride = gridDim.x * blockDim.x;
    for (int e = blockIdx.x * blockDim.x + threadIdx.x; e < NEDGES; e += stride)
        atomicAdd(&g_cnt[er[e]], 1);
}

// Single-block exclusive scan over 100K counts. 1024 threads x 98 elems each.
__global__ __launch_bounds__(1024)
void gcn_scan_kernel() {
    const int PER = 98;
    const int t    = threadIdx.x;
    const int lane = t & 31;
    const int wid  = t >> 5;
    const int base = t * PER;

    int s = 0;
    #pragma unroll 4
    for (int i = 0; i < PER; i++) {
        int idx = base + i;
        if (idx < NROWS) s += g_cnt[idx];
    }

    __shared__ int warp_tot[32];
    int v = s;
    #pragma unroll
    for (int off = 1; off < 32; off <<= 1) {
        int n = __shfl_up_sync(0xFFFFFFFF, v, off);
        if (lane >= off) v += n;
    }
    if (lane == 31) warp_tot[wid] = v;
    __syncthreads();
    if (wid == 0) {
        int w = warp_tot[lane];
        #pragma unroll
        for (int off = 1; off < 32; off <<= 1) {
            int n = __shfl_up_sync(0xFFFFFFFF, w, off);
            if (lane >= off) w += n;
        }
        warp_tot[lane] = w;
    }
    __syncthreads();
    int running = (v - s) + (wid > 0 ? warp_tot[wid - 1] : 0);

    #pragma unroll 4
    for (int i = 0; i < PER; i++) {
        int idx = base + i;
        if (idx < NROWS) {
            int c = g_cnt[idx];
            g_off[idx] = running;
            g_cur[idx] = running;
            running += c;
        }
    }
    if (t == 0) g_off[NROWS] = NEDGES;
}

__global__ __launch_bounds__(256)
void gcn_scatter_kernel(const float* __restrict__ ev,
                        const int*   __restrict__ er,
                        const int*   __restrict__ ec) {
    int stride = gridDim.x * blockDim.x;
    for (int e = blockIdx.x * blockDim.x + threadIdx.x; e < NEDGES; e += stride) {
        int r = er[e];
        int p = atomicAdd(&g_cur[r], 1);
        g_edge[p] = make_uint2((unsigned)ec[e], __float_as_uint(ev[e]));
    }
}

// ---------------------------------------------------------------------------
// Row reduction: one warp per row, lane owns 4 features (float4).
// 4-edge unroll with 2 independent accumulators -> MLP 4 on the h gathers.
// No atomics; one plain 512B store per row (zeros for empty rows).
// ---------------------------------------------------------------------------
__global__ __launch_bounds__(256)
void gcn_row_kernel(float* __restrict__ out) {
    const int w    = (blockIdx.x * blockDim.x + threadIdx.x) >> 5;
    const int lane = threadIdx.x & 31;
    if (w >= NROWS) return;

    int i = g_off[w];
    const int e = g_off[w + 1];

    float4 a0 = make_float4(0.f, 0.f, 0.f, 0.f);
    float4 a1 = make_float4(0.f, 0.f, 0.f, 0.f);

    for (; i + 4 <= e; i += 4) {
        uint2 r0 = __ldg(&g_edge[i + 0]);
        uint2 r1 = __ldg(&g_edge[i + 1]);
        uint2 r2 = __ldg(&g_edge[i + 2]);
        uint2 r3 = __ldg(&g_edge[i + 3]);
        float4 h0 = __ldg((const float4*)(g_h + (size_t)r0.x * NOUT) + lane);
        float4 h1 = __ldg((const float4*)(g_h + (size_t)r1.x * NOUT) + lane);
        float4 h2 = __ldg((const float4*)(g_h + (size_t)r2.x * NOUT) + lane);
        float4 h3 = __ldg((const float4*)(g_h + (size_t)r3.x * NOUT) + lane);
        float v0 = __uint_as_float(r0.y);
        float v1 = __uint_as_float(r1.y);
        float v2 = __uint_as_float(r2.y);
        float v3 = __uint_as_float(r3.y);
        a0.x += v0 * h0.x; a0.y += v0 * h0.y; a0.z += v0 * h0.z; a0.w += v0 * h0.w;
        a1.x += v1 * h1.x; a1.y += v1 * h1.y; a1.z += v1 * h1.z; a1.w += v1 * h1.w;
        a0.x += v2 * h2.x; a0.y += v2 * h2.y; a0.z += v2 * h2.z; a0.w += v2 * h2.w;
        a1.x += v3 * h3.x; a1.y += v3 * h3.y; a1.z += v3 * h3.z; a1.w += v3 * h3.w;
    }
    for (; i < e; i++) {
        uint2 r0 = __ldg(&g_edge[i]);
        float v0 = __uint_as_float(r0.y);
        float4 h0 = __ldg((const float4*)(g_h + (size_t)r0.x * NOUT) + lane);
        a0.x += v0 * h0.x; a0.y += v0 * h0.y; a0.z += v0 * h0.z; a0.w += v0 * h0.w;
    }

    float4 r = make_float4(a0.x + a1.x, a0.y + a1.y, a0.z + a1.z, a0.w + a1.w);
    *(float4*)(out + (size_t)w * NOUT + lane * 4) = r;
}

// ---------------------------------------------------------------------------
// Launch DAG (graph-captured):
//   legacy stream:  zero -> hist -> scan -> scatter ─┐
//   side stream:    GEMM ─────────────────────────────┴─> row kernel
// Fork-join via events so both branches land in the captured graph.
// ---------------------------------------------------------------------------
extern "C" void kernel_launch(void* const* d_in, const int* in_sizes, int n_in,
                              void* d_out, int out_size) {
    const float* x  = (const float*)d_in[0];
    const float* W  = (const float*)d_in[1];
    const float* ev = (const float*)d_in[2];
    const int*   er = (const int*)d_in[3];
    const int*   ec = (const int*)d_in[4];
    float*       out = (float*)d_out;

    cudaStream_t s1;
    cudaStreamCreateWithFlags(&s1, cudaStreamNonBlocking);
    cudaEvent_t e_fork, e_join;
    cudaEventCreateWithFlags(&e_fork, cudaEventDisableTiming);
    cudaEventCreateWithFlags(&e_join, cudaEventDisableTiming);

    // Fork: side stream joins the capture DAG
    cudaEventRecord(e_fork, 0);
    cudaStreamWaitEvent(s1, e_fork, 0);

    // Branch A (side stream): dense projection
    gcn_gemm_kernel<<<(NROWS + 127) / 128, 256, 0, s1>>>(x, W);

    // Branch B (capture stream): edge binning
    gcn_zero_cnt_kernel<<<(NROWS + 1023) / 1024, 1024>>>();
    gcn_hist_kernel<<<2048, 256>>>(er);
    gcn_scan_kernel<<<1, 1024>>>();
    gcn_scatter_kernel<<<2048, 256>>>(ev, er, ec);

    // Join
    cudaEventRecord(e_join, s1);
    cudaStreamWaitEvent(0, e_join, 0);

    // Row reduction (depends on both branches)
    gcn_row_kernel<<<(NROWS * 32 + 255) / 256, 256>>>(out);

    cudaEventDestroy(e_fork);
    cudaEventDestroy(e_join);
    cudaStreamDestroy(s1);
}